// round 4
// baseline (speedup 1.0000x reference)
#include <cuda_runtime.h>

// Problem constants
#define L_   12
#define B_   4
#define H_   12
#define S_   785          // seq incl. CLS
#define NP   784          // LayerNorm width
#define KS   588          // 1-based k-th smallest
#define LN_EPS 1e-5f

// Reduction tiling
#define CH     2                   // row chunks per (b, l, h)
#define ROWS_PER_CHUNK 392         // 784 / CH
#define NPART  (144 * CH)          // 288 partials per b
#define SEG    16
#define PER_SEG (NPART / SEG)      // 18

// Deterministic scratch (device globals — no allocation in kernel_launch)
__device__ float g_part1[B_ * NPART * S_];   // ~3.6 MB
__device__ float g_part2[B_ * SEG * S_];     // ~200 KB

// ---------------------------------------------------------------------------
// Kernel 1: streaming column sums.
// Block = (chunk, lh, b). Thread tid owns column tid (0..784); sums 392 rows.
// Perfectly coalesced: a warp's LDG.32 covers 128 contiguous bytes.
// ---------------------------------------------------------------------------
__global__ __launch_bounds__(800, 2)
void colsum_kernel(const float* __restrict__ att) {
    const int tid   = threadIdx.x;
    if (tid >= S_) return;
    const int chunk = blockIdx.x;     // 0..CH-1
    const int lh    = blockIdx.y;     // 0..143
    const int b     = blockIdx.z;     // 0..3

    const int l = lh / H_;
    const int h = lh - l * H_;
    const int i0 = 1 + chunk * ROWS_PER_CHUNK;   // skip CLS row (i = 0)

    const size_t base =
        ((((size_t)l * B_ + b) * H_ + h) * S_ + i0) * (size_t)S_ + tid;
    const float* __restrict__ p = att + base;

    float a0 = 0.f, a1 = 0.f, a2 = 0.f, a3 = 0.f;
    float a4 = 0.f, a5 = 0.f, a6 = 0.f, a7 = 0.f;

    #pragma unroll 1
    for (int r = 0; r < ROWS_PER_CHUNK / 8; ++r) {
        a0 += p[0 * S_];
        a1 += p[1 * S_];
        a2 += p[2 * S_];
        a3 += p[3 * S_];
        a4 += p[4 * S_];
        a5 += p[5 * S_];
        a6 += p[6 * S_];
        a7 += p[7 * S_];
        p += 8 * S_;
    }
    float sum = ((a0 + a1) + (a2 + a3)) + ((a4 + a5) + (a6 + a7));

    g_part1[((size_t)b * NPART + (size_t)lh * CH + chunk) * S_ + tid] = sum;
}

// ---------------------------------------------------------------------------
// Kernel 2: reduce 288 partials -> 16 per (b, column). Wide grid, coalesced.
// ---------------------------------------------------------------------------
__global__ void reduce1_kernel() {
    const int j   = blockIdx.x * 256 + threadIdx.x;   // column 0..784
    if (j >= S_) return;
    const int seg = blockIdx.y;                       // 0..15
    const int b   = blockIdx.z;

    const float* __restrict__ src =
        g_part1 + ((size_t)b * NPART + (size_t)seg * PER_SEG) * S_ + j;
    float s = 0.f;
    #pragma unroll
    for (int k = 0; k < PER_SEG; ++k) s += src[k * S_];

    g_part2[((size_t)b * SEG + seg) * S_ + j] = s;
}

// ---------------------------------------------------------------------------
// Kernel 3: per-batch finalize. 16-way sum, /144, LayerNorm, rank-based
// kthvalue threshold (sigmoid is monotone, so rank on ln directly), mask.
// One block per b, 1024 threads (784 active columns).
// ---------------------------------------------------------------------------
__global__ __launch_bounds__(1024, 1)
void finalize_kernel(const float* __restrict__ gamma,
                     const float* __restrict__ beta,
                     float* __restrict__ out) {
    __shared__ float red[1024];
    __shared__ float sv[NP];
    __shared__ float s_mu, s_rstd, s_thr;

    const int b = blockIdx.x;
    const int t = threadIdx.x;

    float s = 0.f;
    if (t < NP) {
        // column t of output = column (t+1) of the 785-wide partials
        const float* __restrict__ src = g_part2 + (size_t)b * SEG * S_ + (t + 1);
        #pragma unroll
        for (int k = 0; k < SEG; ++k) s += src[k * S_];
        s *= (1.0f / (L_ * H_));    // mean over heads then layers
    }

    // mean
    red[t] = (t < NP) ? s : 0.f;
    __syncthreads();
    for (int o = 512; o > 0; o >>= 1) {
        if (t < o) red[t] += red[t + o];
        __syncthreads();
    }
    if (t == 0) s_mu = red[0] / NP;
    __syncthreads();
    const float mu = s_mu;

    // variance
    const float d = (t < NP) ? (s - mu) : 0.f;
    red[t] = d * d;
    __syncthreads();
    for (int o = 512; o > 0; o >>= 1) {
        if (t < o) red[t] += red[t + o];
        __syncthreads();
    }
    if (t == 0) s_rstd = rsqrtf(red[0] / NP + LN_EPS);
    __syncthreads();

    if (t < NP) sv[t] = d * s_rstd * gamma[t] + beta[t];
    __syncthreads();

    // k-th smallest by rank counting (ties handled: rank interval covers k-1)
    if (t < NP) {
        const float v = sv[t];
        int cl = 0, ce = 0;
        #pragma unroll 4
        for (int j = 0; j < NP; ++j) {
            const float x = sv[j];
            cl += (x < v);
            ce += (x == v);
        }
        if (cl <= (KS - 1) && cl + ce > (KS - 1)) s_thr = v;
    }
    __syncthreads();

    if (t < NP) out[(size_t)b * NP + t] = (sv[t] > s_thr) ? 1.0f : 0.0f;
}

// ---------------------------------------------------------------------------
extern "C" void kernel_launch(void* const* d_in, const int* in_sizes, int n_in,
                              void* d_out, int out_size) {
    const float* att   = (const float*)d_in[0];
    const float* gamma = (const float*)d_in[1];
    const float* beta  = (const float*)d_in[2];
    float* out = (float*)d_out;

    colsum_kernel<<<dim3(CH, 144, B_), 800>>>(att);
    reduce1_kernel<<<dim3(4, SEG, B_), 256>>>();
    finalize_kernel<<<B_, 1024>>>(gamma, beta, out);
}